// round 1
// baseline (speedup 1.0000x reference)
#include <cuda_runtime.h>
#include <math.h>

#define BB 64
#define LCC 1024
#define LQQ 128
#define DDIM 128
#define NSLICE 8

// Scratch (device globals, allocation-free)
__device__ float g_S[(size_t)BB * LCC * LQQ];         // 33.5 MB raw logits
__device__ float g_T[BB * LQQ * DDIM];                // final T
__device__ float g_Tpart[NSLICE][BB * LQQ * DDIM];    // split-K partials
__device__ float g_zpart[NSLICE][BB * LQQ];           // split-K colsum partials
__device__ float g_cw1[BB * LCC];
__device__ float g_qw2[BB * LQQ];

// ---------------------------------------------------------------------------
// K1: cw1[b,i] = c_rep[b,i,:]·w1 ; qw2[b,j] = q_rep[b,j,:]·w2  (warp per row)
// ---------------------------------------------------------------------------
__global__ __launch_bounds__(256) void k1_rank1(const float* __restrict__ c_rep,
                                                const float* __restrict__ q_rep,
                                                const float* __restrict__ w) {
    int gw   = (blockIdx.x * blockDim.x + threadIdx.x) >> 5;
    int lane = threadIdx.x & 31;
    const int NC = BB * LCC;
    if (gw < NC) {
        const float* row = c_rep + (size_t)gw * DDIM;
        float s = 0.f;
#pragma unroll
        for (int k = 0; k < 4; k++) s = fmaf(row[lane + 32 * k], w[lane + 32 * k], s);
#pragma unroll
        for (int o = 16; o > 0; o >>= 1) s += __shfl_xor_sync(0xffffffffu, s, o);
        if (lane == 0) g_cw1[gw] = s;
    } else if (gw < NC + BB * LQQ) {
        int r = gw - NC;
        const float* row = q_rep + (size_t)r * DDIM;
        float s = 0.f;
#pragma unroll
        for (int k = 0; k < 4; k++) s = fmaf(row[lane + 32 * k], w[DDIM + lane + 32 * k], s);
#pragma unroll
        for (int o = 16; o > 0; o >>= 1) s += __shfl_xor_sync(0xffffffffu, s, o);
        if (lane == 0) g_qw2[r] = s;
    }
}

// ---------------------------------------------------------------------------
// K2: S[b,i,j] = cw1 + qw2 + sum_d (c[i,d]*w3[d]) * q[j,d]
// Block: 64 i x 128 j, K=128.  Thread: 4i x 8j register tile.
// ---------------------------------------------------------------------------
__global__ __launch_bounds__(256) void k2_S(const float* __restrict__ c_rep,
                                            const float* __restrict__ q_rep,
                                            const float* __restrict__ w) {
    int b  = blockIdx.y;
    int i0 = blockIdx.x * 64;
    __shared__ float cs[32][68];    // [k][i]  (c * w3), transposed
    __shared__ float qs[32][132];   // [k][j]  transposed
    int t  = threadIdx.x;
    int tx = t & 15;     // j-group (8 j)
    int ty = t >> 4;     // i-group (4 i)
    float acc[4][8];
#pragma unroll
    for (int a = 0; a < 4; a++)
#pragma unroll
        for (int c = 0; c < 8; c++) acc[a][c] = 0.f;

    const float* cb = c_rep + ((size_t)b * LCC + i0) * DDIM;
    const float* qb = q_rep + (size_t)b * LQQ * DDIM;
    const float* w3 = w + 2 * DDIM;

    for (int k0 = 0; k0 < DDIM; k0 += 32) {
#pragma unroll
        for (int l = 0; l < 2; l++) {                 // c tile: 64x32, transpose+scale
            int idx = t + l * 256;
            int i   = idx >> 3;
            int kq  = idx & 7;
            float4 v = *(const float4*)(cb + (size_t)i * DDIM + k0 + kq * 4);
            int kk = kq * 4;
            cs[kk + 0][i] = v.x * w3[k0 + kk + 0];
            cs[kk + 1][i] = v.y * w3[k0 + kk + 1];
            cs[kk + 2][i] = v.z * w3[k0 + kk + 2];
            cs[kk + 3][i] = v.w * w3[k0 + kk + 3];
        }
#pragma unroll
        for (int l = 0; l < 4; l++) {                 // q tile: 128x32, transpose
            int idx = t + l * 256;
            int j   = idx >> 3;
            int kq  = idx & 7;
            float4 v = *(const float4*)(qb + (size_t)j * DDIM + k0 + kq * 4);
            int kk = kq * 4;
            qs[kk + 0][j] = v.x; qs[kk + 1][j] = v.y;
            qs[kk + 2][j] = v.z; qs[kk + 3][j] = v.w;
        }
        __syncthreads();
#pragma unroll
        for (int k = 0; k < 32; k++) {
            float af[4], bf[8];
#pragma unroll
            for (int a = 0; a < 4; a++) af[a] = cs[k][ty * 4 + a];
#pragma unroll
            for (int c = 0; c < 8; c++) bf[c] = qs[k][tx * 8 + c];
#pragma unroll
            for (int a = 0; a < 4; a++)
#pragma unroll
                for (int c = 0; c < 8; c++)
                    acc[a][c] = fmaf(af[a], bf[c], acc[a][c]);
        }
        __syncthreads();
    }
    float qwf[8];
#pragma unroll
    for (int c = 0; c < 8; c++) qwf[c] = g_qw2[b * LQQ + tx * 8 + c];
#pragma unroll
    for (int a = 0; a < 4; a++) {
        int i = ty * 4 + a;
        float cw = g_cw1[b * LCC + i0 + i];
        float* o = g_S + ((size_t)b * LCC + i0 + i) * LQQ + tx * 8;
        float4 v0 = make_float4(acc[a][0] + cw + qwf[0], acc[a][1] + cw + qwf[1],
                                acc[a][2] + cw + qwf[2], acc[a][3] + cw + qwf[3]);
        float4 v1 = make_float4(acc[a][4] + cw + qwf[4], acc[a][5] + cw + qwf[5],
                                acc[a][6] + cw + qwf[6], acc[a][7] + cw + qwf[7]);
        *(float4*)o       = v0;
        *(float4*)(o + 4) = v1;
    }
}

// ---------------------------------------------------------------------------
// K3: split-K partials of T numerator and column softmax denominator.
//   E[k,j] = c_mask[k] ? 0 : exp(S[k,j])   (no max needed: |S| <~ 7)
//   Tpart[slice][j,d] = sum_{k in slice} E[k,j] * c[k,d]
//   zpart[slice][j]   = sum_{k in slice} E[k,j]
// Block: slice of 128 k rows; 128 j x 128 d; thread: 8j x 8d tile.
// ---------------------------------------------------------------------------
__global__ __launch_bounds__(256) void k3_Tpart(const float* __restrict__ c_rep,
                                                const int* __restrict__ c_mask) {
    int b     = blockIdx.y;
    int slice = blockIdx.x;
    int kbase = slice * 128;
    __shared__ float es[32][132];   // exp(S) [k][j]
    __shared__ float cs[32][132];   // c_rep  [k][d]
    int t  = threadIdx.x;
    int tx = t & 15;   // d-group (8 d)
    int ty = t >> 4;   // j-group (8 j)
    float acc[8][8];
    float zacc[8];
#pragma unroll
    for (int jj = 0; jj < 8; jj++) {
        zacc[jj] = 0.f;
#pragma unroll
        for (int dd = 0; dd < 8; dd++) acc[jj][dd] = 0.f;
    }

    for (int k0 = 0; k0 < 128; k0 += 32) {
#pragma unroll
        for (int l = 0; l < 4; l++) {
            int idx = t + l * 256;
            int kk  = idx >> 5;
            int jq  = idx & 31;
            int krow = kbase + k0 + kk;
            float4 v = *(const float4*)(g_S + ((size_t)b * LCC + krow) * LQQ + jq * 4);
            float m = c_mask[b * LCC + krow] ? 0.f : 1.f;
            es[kk][jq * 4 + 0] = m * expf(v.x);
            es[kk][jq * 4 + 1] = m * expf(v.y);
            es[kk][jq * 4 + 2] = m * expf(v.z);
            es[kk][jq * 4 + 3] = m * expf(v.w);
        }
#pragma unroll
        for (int l = 0; l < 4; l++) {
            int idx = t + l * 256;
            int kk  = idx >> 5;
            int dq  = idx & 31;
            int krow = kbase + k0 + kk;
            float4 v = *(const float4*)(c_rep + ((size_t)b * LCC + krow) * DDIM + dq * 4);
            cs[kk][dq * 4 + 0] = v.x; cs[kk][dq * 4 + 1] = v.y;
            cs[kk][dq * 4 + 2] = v.z; cs[kk][dq * 4 + 3] = v.w;
        }
        __syncthreads();
#pragma unroll
        for (int k = 0; k < 32; k++) {
            float ef[8], cf[8];
#pragma unroll
            for (int jj = 0; jj < 8; jj++) ef[jj] = es[k][ty * 8 + jj];
#pragma unroll
            for (int dd = 0; dd < 8; dd++) cf[dd] = cs[k][tx * 8 + dd];
#pragma unroll
            for (int jj = 0; jj < 8; jj++) zacc[jj] += ef[jj];
#pragma unroll
            for (int jj = 0; jj < 8; jj++)
#pragma unroll
                for (int dd = 0; dd < 8; dd++)
                    acc[jj][dd] = fmaf(ef[jj], cf[dd], acc[jj][dd]);
        }
        __syncthreads();
    }
#pragma unroll
    for (int jj = 0; jj < 8; jj++) {
        int j = ty * 8 + jj;
        float* dst = &g_Tpart[slice][((size_t)(b * LQQ + j)) * DDIM + tx * 8];
        *(float4*)dst       = make_float4(acc[jj][0], acc[jj][1], acc[jj][2], acc[jj][3]);
        *(float4*)(dst + 4) = make_float4(acc[jj][4], acc[jj][5], acc[jj][6], acc[jj][7]);
    }
    if (tx == 0) {
#pragma unroll
        for (int jj = 0; jj < 8; jj++)
            g_zpart[slice][b * LQQ + ty * 8 + jj] = zacc[jj];
    }
}

// ---------------------------------------------------------------------------
// K3r: reduce split-K partials -> T[b,j,d] = (sum_s num) / (sum_s z)
// ---------------------------------------------------------------------------
__global__ __launch_bounds__(256) void k3_reduce() {
    int idx = blockIdx.x * 256 + threadIdx.x;        // B*LQ*D = 1,048,576
    if (idx < BB * LQQ * DDIM) {
        int bj = idx / DDIM;
        float num = 0.f, z = 0.f;
#pragma unroll
        for (int s = 0; s < NSLICE; s++) num += g_Tpart[s][idx];
#pragma unroll
        for (int s = 0; s < NSLICE; s++) z += g_zpart[s][bj];
        g_T[idx] = num / z;
    }
}

// ---------------------------------------------------------------------------
// K4: row softmax S1, then fused dual-GEMM A = S1*q, Batt = S1*T, and output
// concat [c, A, c*A, c*Batt].  Block: 64 i rows; thread tile: 4i x 8d (x2).
// ---------------------------------------------------------------------------
__global__ __launch_bounds__(256) void k4_out(const float* __restrict__ c_rep,
                                              const float* __restrict__ q_rep,
                                              const int* __restrict__ q_mask,
                                              float* __restrict__ out) {
    int b  = blockIdx.y;
    int i0 = blockIdx.x * 64;
    extern __shared__ float sm[];
    float* ps = sm;                   // [128 j][68 i]  exp values (transposed)
    float* qs = sm + 128 * 68;        // [32 j][132 d]  chunk
    float* ts = qs + 32 * 132;        // [32 j][132 d]  chunk
    __shared__ float qmf[128];
    __shared__ float zp[64][4];
    __shared__ float zrow[64];
    int t = threadIdx.x;
    if (t < 128) qmf[t] = q_mask[b * LQQ + t] ? 0.f : 1.f;
    __syncthreads();

    // phase A: load S rows, mask+exp, transpose into ps, row sums
    {
        int i  = t >> 2;              // 0..63
        int q4 = t & 3;
        const float4* srow = (const float4*)(g_S + ((size_t)(b * LCC + i0 + i)) * LQQ);
        float part = 0.f;
#pragma unroll
        for (int l = 0; l < 8; l++) {
            int f = q4 + l * 4;       // float4 index 0..31 (coalesced across quad)
            float4 v = srow[f];
            int j = f * 4;
            float e0 = qmf[j + 0] * expf(v.x);
            float e1 = qmf[j + 1] * expf(v.y);
            float e2 = qmf[j + 2] * expf(v.z);
            float e3 = qmf[j + 3] * expf(v.w);
            ps[(j + 0) * 68 + i] = e0;
            ps[(j + 1) * 68 + i] = e1;
            ps[(j + 2) * 68 + i] = e2;
            ps[(j + 3) * 68 + i] = e3;
            part += e0 + e1 + e2 + e3;
        }
        zp[i][q4] = part;
    }
    __syncthreads();
    if (t < 64) zrow[t] = 1.f / (zp[t][0] + zp[t][1] + zp[t][2] + zp[t][3]);

    int tx = t & 15, ty = t >> 4;
    float accA[4][8], accB[4][8];
#pragma unroll
    for (int a = 0; a < 4; a++)
#pragma unroll
        for (int c = 0; c < 8; c++) { accA[a][c] = 0.f; accB[a][c] = 0.f; }

    for (int j0 = 0; j0 < 128; j0 += 32) {
        __syncthreads();   // protect qs/ts from previous iteration's readers (and order zrow)
#pragma unroll
        for (int l = 0; l < 4; l++) {
            int idx = t + l * 256;
            int jj  = idx >> 5;
            int dq  = idx & 31;
            float4 v = *(const float4*)(q_rep + ((size_t)(b * LQQ + j0 + jj)) * DDIM + dq * 4);
            *(float4*)(qs + jj * 132 + dq * 4) = v;
            float4 u = *(const float4*)(g_T + ((size_t)(b * LQQ + j0 + jj)) * DDIM + dq * 4);
            *(float4*)(ts + jj * 132 + dq * 4) = u;
        }
        __syncthreads();
#pragma unroll
        for (int k = 0; k < 32; k++) {
            float pf[4], qf[8], tf[8];
#pragma unroll
            for (int a = 0; a < 4; a++) pf[a] = ps[(j0 + k) * 68 + ty * 4 + a];
#pragma unroll
            for (int c = 0; c < 8; c++) qf[c] = qs[k * 132 + tx * 8 + c];
#pragma unroll
            for (int c = 0; c < 8; c++) tf[c] = ts[k * 132 + tx * 8 + c];
#pragma unroll
            for (int a = 0; a < 4; a++)
#pragma unroll
                for (int c = 0; c < 8; c++) {
                    accA[a][c] = fmaf(pf[a], qf[c], accA[a][c]);
                    accB[a][c] = fmaf(pf[a], tf[c], accB[a][c]);
                }
        }
    }
    __syncthreads();

    // epilogue: out[b,i, 0:128]=c ; [128:256]=A ; [256:384]=c*A ; [384:512]=c*Batt
#pragma unroll
    for (int a = 0; a < 4; a++) {
        int i = ty * 4 + a;
        float zi = zrow[i];
        const float* crow = c_rep + ((size_t)(b * LCC + i0 + i)) * DDIM + tx * 8;
        float4 c0 = *(const float4*)crow;
        float4 c1 = *(const float4*)(crow + 4);
        float cv[8] = {c0.x, c0.y, c0.z, c0.w, c1.x, c1.y, c1.z, c1.w};
        float av[8], bv[8];
#pragma unroll
        for (int c = 0; c < 8; c++) { av[c] = accA[a][c] * zi; bv[c] = accB[a][c] * zi; }
        float* ob = out + ((size_t)(b * LCC + i0 + i)) * (4 * DDIM);
        *(float4*)(ob + tx * 8)               = c0;
        *(float4*)(ob + tx * 8 + 4)           = c1;
        *(float4*)(ob + DDIM + tx * 8)        = make_float4(av[0], av[1], av[2], av[3]);
        *(float4*)(ob + DDIM + tx * 8 + 4)    = make_float4(av[4], av[5], av[6], av[7]);
        *(float4*)(ob + 2 * DDIM + tx * 8)    = make_float4(cv[0] * av[0], cv[1] * av[1], cv[2] * av[2], cv[3] * av[3]);
        *(float4*)(ob + 2 * DDIM + tx * 8 + 4) = make_float4(cv[4] * av[4], cv[5] * av[5], cv[6] * av[6], cv[7] * av[7]);
        *(float4*)(ob + 3 * DDIM + tx * 8)    = make_float4(cv[0] * bv[0], cv[1] * bv[1], cv[2] * bv[2], cv[3] * bv[3]);
        *(float4*)(ob + 3 * DDIM + tx * 8 + 4) = make_float4(cv[4] * bv[4], cv[5] * bv[5], cv[6] * bv[6], cv[7] * bv[7]);
    }
}

// ---------------------------------------------------------------------------
extern "C" void kernel_launch(void* const* d_in, const int* in_sizes, int n_in,
                              void* d_out, int out_size) {
    const float* c_rep  = (const float*)d_in[0];
    const float* q_rep  = (const float*)d_in[1];
    const int*   c_mask = (const int*)d_in[2];
    const int*   q_mask = (const int*)d_in[3];
    const float* w      = (const float*)d_in[4];
    float* out = (float*)d_out;

    // K1: rank-1 projections
    {
        int total_warps = BB * LCC + BB * LQQ;       // 73728
        int blocks = total_warps / 8;                // 256 threads = 8 warps
        k1_rank1<<<blocks, 256>>>(c_rep, q_rep, w);
    }
    // K2: logits S
    {
        dim3 g(LCC / 64, BB);
        k2_S<<<g, 256>>>(c_rep, q_rep, w);
    }
    // K3: T partials (split-K over LC) + column softmax denominators
    {
        dim3 g(NSLICE, BB);
        k3_Tpart<<<g, 256>>>(c_rep, c_mask);
    }
    // K3r: reduce
    k3_reduce<<<(BB * LQQ * DDIM) / 256, 256>>>();
    // K4: row softmax + dual GEMM + output assembly
    {
        int smem = (128 * 68 + 32 * 132 + 32 * 132) * 4;  // 68608 B
        cudaFuncSetAttribute(k4_out, cudaFuncAttributeMaxDynamicSharedMemorySize, smem);
        dim3 g(LCC / 64, BB);
        k4_out<<<g, 256, smem>>>(c_rep, q_rep, q_mask, out);
    }
}